// round 12
// baseline (speedup 1.0000x reference)
#include <cuda_runtime.h>
#include <cuda_bf16.h>
#include <cstdint>

#define HH 256
#define WW 512
#define CIN 32
#define COUT 64
#define KK 9
#define BB 2
#define HWSZ (HH * WW)           /* 131072 */
#define NPIX (BB * HWSZ)         /* 262144 */
#define CK 288                   /* CIN*KK */
#define TPX 128                  /* pixels per tile */
#define HPX 64                   /* pixels per half (pipeline unit) */
#define NT (NPIX / TPX)          /* 2048 tiles */
#define THREADS 512

#define SB  296                  /* bf16 elements per smem row (288 + 8 pad) */
#define SBB (SB * 2)             /* 592 bytes per row; 16B-aligned, conflict-free ldmatrix */

/* ---- shared memory byte map ----
   A buffers: 2 x (hi plane + lo plane), each plane 64 rows x 592 B = 37888 B */
#define APLANE 37888
#define ABUF   (2 * APLANE)                /* 75776 per buffer */
#define A_BASE 1024
#define B_HI   (A_BASE + 2 * ABUF)         /* 1024 + 151552 */
#define B_LO   (B_HI + COUT * SBB)         /* +37888 */
#define SMEM_BYTES (B_LO + COUT * SBB)     /* 228352 */

// Scratch: transposed input  xt[b][h][w][c]  (33.5 MB)
__device__ float g_xt[(size_t)NPIX * CIN];

__device__ __forceinline__ uint32_t smem_u32(const void* p) {
    uint32_t a;
    asm("{ .reg .u64 t; cvta.to.shared.u64 t, %1; cvt.u32.u64 %0, t; }"
        : "=r"(a) : "l"(p));
    return a;
}

__device__ __forceinline__ void ldm4(uint32_t& r0, uint32_t& r1,
                                     uint32_t& r2, uint32_t& r3,
                                     uint32_t addr) {
    asm volatile("ldmatrix.sync.aligned.m8n8.x4.shared.b16 {%0,%1,%2,%3}, [%4];"
                 : "=r"(r0), "=r"(r1), "=r"(r2), "=r"(r3) : "r"(addr));
}

__device__ __forceinline__ void mma16816(float* d,
                                         uint32_t a0, uint32_t a1,
                                         uint32_t a2, uint32_t a3,
                                         uint32_t b0, uint32_t b1) {
    asm volatile(
        "mma.sync.aligned.m16n8k16.row.col.f32.bf16.bf16.f32 "
        "{%0,%1,%2,%3}, {%4,%5,%6,%7}, {%8,%9}, {%0,%1,%2,%3};"
        : "+f"(d[0]), "+f"(d[1]), "+f"(d[2]), "+f"(d[3])
        : "r"(a0), "r"(a1), "r"(a2), "r"(a3), "r"(b0), "r"(b1));
}

// ---------------------------------------------------------------------------
// Kernel 1: transpose [B, C, H, W] -> [B, H*W, C]
// ---------------------------------------------------------------------------
__global__ void transpose_kernel(const float* __restrict__ x) {
    __shared__ float tile[32][33];
    const int b  = blockIdx.y;
    const int s0 = blockIdx.x * 32;
    const int tx = threadIdx.x;
    const int ty = threadIdx.y;
    const float* xb = x + (size_t)b * CIN * HWSZ;
#pragma unroll
    for (int i = 0; i < 4; i++) {
        const int c = ty + i * 8;
        tile[c][tx] = __ldg(&xb[(size_t)c * HWSZ + s0 + tx]);
    }
    __syncthreads();
    float* xtb = g_xt + ((size_t)b * HWSZ + s0) * CIN;
#pragma unroll
    for (int i = 0; i < 4; i++) {
        const int srow = ty + i * 8;
        xtb[srow * CIN + tx] = tile[tx][srow];
    }
}

// ---------------------------------------------------------------------------
// Kernel 2: warp-specialized gather/HMMA pipeline
//   warps 0-7: producers (bilinear gather -> bf16 hi/lo into A buf)
//   warps 8-15: consumers (3-term bf16 HMMA + direct store)
// ---------------------------------------------------------------------------
extern __shared__ char smem[];

__global__ void __launch_bounds__(THREADS, 1) mapped_conv_kernel(
    const float* __restrict__ smap,     // [OH*OW, K, 2]
    const float* __restrict__ weight,   // [COUT, CIN, K]
    const float* __restrict__ bias,     // [COUT]
    float* __restrict__ out)            // [B, COUT, OH*OW]
{
    const int tid  = threadIdx.x;
    const int warp = tid >> 5;
    const int lane = tid & 31;
    const uint32_t sbase = smem_u32(smem);

    // ---- one-time: weights -> B_HI/B_LO at [o][k*32+c] bf16
    for (int idx = tid; idx < COUT * CK; idx += THREADS) {
        const int o = idx / CK;
        const int r = idx - o * CK;      // c*KK + k
        const int c = r / KK;
        const int k = r - c * KK;
        const float w = weight[idx];
        const __nv_bfloat16 hi = __float2bfloat16(w);
        const __nv_bfloat16 lo = __float2bfloat16(w - __bfloat162float(hi));
        const int off = o * SBB + (k * CIN + c) * 2;
        *reinterpret_cast<__nv_bfloat16*>(smem + B_HI + off) = hi;
        *reinterpret_cast<__nv_bfloat16*>(smem + B_LO + off) = lo;
    }

    // ---- consumer geometry (warps 8-15): 64px x 64out, warp-tile 32x16
    const int cw = warp - 8;             // 0..7
    const int m0 = (cw >> 2) * 32;       // 0 or 32
    const int n0 = (cw & 3) * 16;        // 0,16,32,48
    const int qr = lane >> 2;
    const int qc = lane & 3;
    const uint32_t aRow = (uint32_t)((m0 + (lane & 15)) * SBB
                                     + ((lane >> 4) << 4));
    const uint32_t bRow = (uint32_t)((n0 + (lane & 7) + ((lane >> 4) << 3)) * SBB
                                     + (((lane >> 3) & 1) << 4));
    float bs[2][2];
#pragma unroll
    for (int nt = 0; nt < 2; nt++) {
        const int o0 = (n0 + nt * 8 + qc * 2) & (COUT - 1);
        bs[nt][0] = __ldg(&bias[o0]);
        bs[nt][1] = __ldg(&bias[o0 + 1]);
    }

    // ---- producer geometry (warps 0-7): half-warp per pixel, lane -> 2 ch
    const int hl = lane & 15;
    const int ph = lane >> 4;

    __syncthreads();

    // ---- half-tile pipeline: produce half s, consume half s-1
    const int nt_cta   = (NT - blockIdx.x + gridDim.x - 1) / gridDim.x;
    const int nhalves  = 2 * nt_cta;

    for (int s = 0; s <= nhalves; s++) {
        // ================= producers =================
        if (warp < 8 && s < nhalves) {
            const int t   = blockIdx.x + (s >> 1) * gridDim.x;
            const int gp0 = t * TPX + (s & 1) * HPX;
            const int b   = gp0 >> 17;
            const int s0  = gp0 & (HWSZ - 1);
            const float2* __restrict__ xb2 =
                reinterpret_cast<const float2*>(g_xt + (size_t)b * HWSZ * CIN) + hl;
            char* abuf = smem + A_BASE + (s & 1) * ABUF;

#pragma unroll 1
            for (int i = 0; i < 4; i++) {
                const int pp = warp * 8 + i * 2 + ph;   // row in buffer [0,64)
                const float2* __restrict__ smp =
                    reinterpret_cast<const float2*>(smap) + (s0 + pp) * KK;
                char* arow_hi = abuf + pp * SBB + hl * 4;
                char* arow_lo = arow_hi + APLANE;

#pragma unroll
                for (int k = 0; k < KK; k++) {
                    const float2 sxy = __ldg(&smp[k]);
                    const float bx = floorf(sxy.x), by = floorf(sxy.y);
                    const float fx = sxy.x - bx,  fy = sxy.y - by;
                    const int x0 = (int)bx,  y0 = (int)by;
                    const int x1 = min(x0 + 1, WW - 1);
                    const int y1 = min(y0 + 1, HH - 1);

                    const int i00 = (y0 << 13) + (x0 << 4);
                    const int i01 = (y0 << 13) + (x1 << 4);
                    const int i10 = (y1 << 13) + (x0 << 4);
                    const int i11 = (y1 << 13) + (x1 << 4);

                    const float2 v00 = __ldg(xb2 + i00);
                    const float2 v01 = __ldg(xb2 + i01);
                    const float2 v10 = __ldg(xb2 + i10);
                    const float2 v11 = __ldg(xb2 + i11);

                    float2 v;
                    {
                        const float tx0 = fmaf(fx, v01.x - v00.x, v00.x);
                        const float bx0 = fmaf(fx, v11.x - v10.x, v10.x);
                        v.x = fmaf(fy, bx0 - tx0, tx0);
                        const float ty0 = fmaf(fx, v01.y - v00.y, v00.y);
                        const float by0 = fmaf(fx, v11.y - v10.y, v10.y);
                        v.y = fmaf(fy, by0 - ty0, ty0);
                    }

                    const __nv_bfloat162 hi2 = __float22bfloat162_rn(v);
                    const float2 hif = __bfloat1622float2(hi2);
                    const __nv_bfloat162 lo2 = __float22bfloat162_rn(
                        make_float2(v.x - hif.x, v.y - hif.y));

                    *reinterpret_cast<__nv_bfloat162*>(arow_hi + k * 64) = hi2;
                    *reinterpret_cast<__nv_bfloat162*>(arow_lo + k * 64) = lo2;
                }
            }
        }

        // ================= consumers =================
        if (warp >= 8 && s >= 1) {
            const int cs  = s - 1;
            const int t   = blockIdx.x + (cs >> 1) * gridDim.x;
            const int gp0 = t * TPX + (cs & 1) * HPX;
            const int b   = gp0 >> 17;
            const int s0  = gp0 & (HWSZ - 1);
            const uint32_t abase = sbase + A_BASE + (cs & 1) * ABUF;

            float acc[2][2][4];
#pragma unroll
            for (int a = 0; a < 2; a++)
#pragma unroll
                for (int c = 0; c < 2; c++)
#pragma unroll
                    for (int r = 0; r < 4; r++) acc[a][c][r] = 0.0f;

#pragma unroll
            for (int term = 0; term < 3; term++) {
                const uint32_t aBase = abase + ((term == 1) ? APLANE : 0) + aRow;
                const uint32_t bBase = sbase + ((term == 2) ? B_LO : B_HI) + bRow;
#pragma unroll
                for (int ks = 0; ks < 18; ks++) {
                    const uint32_t kb = ks * 32;
                    uint32_t a0, a1, a2, a3, c0, c1, c2, c3, b0, b1, b2, b3;
                    ldm4(a0, a1, a2, a3, aBase + kb);
                    ldm4(c0, c1, c2, c3, aBase + 16 * SBB + kb);
                    ldm4(b0, b1, b2, b3, bBase + kb);
                    mma16816(acc[0][0], a0, a1, a2, a3, b0, b1);
                    mma16816(acc[0][1], a0, a1, a2, a3, b2, b3);
                    mma16816(acc[1][0], c0, c1, c2, c3, b0, b1);
                    mma16816(acc[1][1], c0, c1, c2, c3, b2, b3);
                }
            }

            // direct stores + bias
            float* ob = out + (size_t)(b * COUT) * HWSZ + s0;
#pragma unroll
            for (int mt = 0; mt < 2; mt++) {
                const int pixA = m0 + mt * 16 + qr;
#pragma unroll
                for (int nt = 0; nt < 2; nt++) {
                    const int o0 = n0 + nt * 8 + qc * 2;
                    ob[(size_t)o0 * HWSZ + pixA]           = acc[mt][nt][0] + bs[nt][0];
                    ob[(size_t)(o0 + 1) * HWSZ + pixA]     = acc[mt][nt][1] + bs[nt][1];
                    ob[(size_t)o0 * HWSZ + pixA + 8]       = acc[mt][nt][2] + bs[nt][0];
                    ob[(size_t)(o0 + 1) * HWSZ + pixA + 8] = acc[mt][nt][3] + bs[nt][1];
                }
            }
        }

        __syncthreads();   // step boundary: buf[s&1] now full, buf[(s+1)&1] free
    }
}

// ---------------------------------------------------------------------------
// launch
// ---------------------------------------------------------------------------
extern "C" void kernel_launch(void* const* d_in, const int* in_sizes, int n_in,
                              void* d_out, int out_size) {
    const float* x = nullptr;
    const float* weight = nullptr;
    const float* bias = nullptr;
    const float* smap = nullptr;
    for (int i = 0; i < n_in; i++) {
        switch (in_sizes[i]) {
            case 8388608: x      = (const float*)d_in[i]; break;
            case 18432:   weight = (const float*)d_in[i]; break;
            case 64:      bias   = (const float*)d_in[i]; break;
            case 2359296: smap   = (const float*)d_in[i]; break;
            default: break;
        }
    }
    float* out = (float*)d_out;

    static int n_sm = 0;
    if (n_sm == 0) {
        cudaFuncSetAttribute(mapped_conv_kernel,
                             cudaFuncAttributeMaxDynamicSharedMemorySize,
                             SMEM_BYTES);
        cudaDeviceGetAttribute(&n_sm, cudaDevAttrMultiProcessorCount, 0);
        if (n_sm <= 0) n_sm = 148;
    }

    // 1) transpose x -> g_xt
    {
        dim3 grid(HWSZ / 32, BB);
        dim3 block(32, 8);
        transpose_kernel<<<grid, block>>>(x);
    }

    // 2) warp-specialized gather/GEMM pipeline: persistent, 1 CTA/SM
    mapped_conv_kernel<<<n_sm, THREADS, SMEM_BYTES>>>(smap, weight, bias, out);
}

// round 13
// speedup vs baseline: 1.4623x; 1.4623x over previous
#include <cuda_runtime.h>
#include <cuda_bf16.h>
#include <cstdint>

#define HH 256
#define WW 512
#define CIN 32
#define COUT 64
#define KK 9
#define BB 2
#define HWSZ (HH * WW)           /* 131072 */
#define NPIX (BB * HWSZ)         /* 262144 */
#define CK 288                   /* CIN*KK */
#define TPX 128                  /* pixels per tile */
#define HPX 64                   /* pixels per half (pipeline unit) */
#define NT (NPIX / TPX)          /* 2048 tiles */
#define THREADS 512

#define SB  296                  /* bf16 elements per smem row (288 + 8 pad) */
#define SBB (SB * 2)             /* 592 bytes per row; 16B-aligned, conflict-free ldmatrix */

/* ---- shared memory byte map ----
   A buffers: 2 x (hi plane + lo plane), each plane 64 rows x 592 B = 37888 B */
#define APLANE 37888
#define ABUF   (2 * APLANE)                /* 75776 per buffer */
#define A_BASE 1024
#define B_HI   (A_BASE + 2 * ABUF)         /* 1024 + 151552 */
#define B_LO   (B_HI + COUT * SBB)         /* +37888 */
#define SMEM_BYTES (B_LO + COUT * SBB)     /* 228352 */

// Scratch: transposed input  xt[b][h][w][c]  (33.5 MB)
__device__ float g_xt[(size_t)NPIX * CIN];

__device__ __forceinline__ uint32_t smem_u32(const void* p) {
    uint32_t a;
    asm("{ .reg .u64 t; cvta.to.shared.u64 t, %1; cvt.u32.u64 %0, t; }"
        : "=r"(a) : "l"(p));
    return a;
}

__device__ __forceinline__ void ldm4(uint32_t& r0, uint32_t& r1,
                                     uint32_t& r2, uint32_t& r3,
                                     uint32_t addr) {
    asm volatile("ldmatrix.sync.aligned.m8n8.x4.shared.b16 {%0,%1,%2,%3}, [%4];"
                 : "=r"(r0), "=r"(r1), "=r"(r2), "=r"(r3) : "r"(addr));
}

__device__ __forceinline__ void mma16816(float* d,
                                         uint32_t a0, uint32_t a1,
                                         uint32_t a2, uint32_t a3,
                                         uint32_t b0, uint32_t b1) {
    asm volatile(
        "mma.sync.aligned.m16n8k16.row.col.f32.bf16.bf16.f32 "
        "{%0,%1,%2,%3}, {%4,%5,%6,%7}, {%8,%9}, {%0,%1,%2,%3};"
        : "+f"(d[0]), "+f"(d[1]), "+f"(d[2]), "+f"(d[3])
        : "r"(a0), "r"(a1), "r"(a2), "r"(a3), "r"(b0), "r"(b1));
}

__device__ __forceinline__ uint32_t bf2_u32(__nv_bfloat162 v) {
    uint32_t u;
    __builtin_memcpy(&u, &v, 4);
    return u;
}

// ---------------------------------------------------------------------------
// Kernel 1: transpose [B, C, H, W] -> [B, H*W, C]
// ---------------------------------------------------------------------------
__global__ void transpose_kernel(const float* __restrict__ x) {
    __shared__ float tile[32][33];
    const int b  = blockIdx.y;
    const int s0 = blockIdx.x * 32;
    const int tx = threadIdx.x;
    const int ty = threadIdx.y;
    const float* xb = x + (size_t)b * CIN * HWSZ;
#pragma unroll
    for (int i = 0; i < 4; i++) {
        const int c = ty + i * 8;
        tile[c][tx] = __ldg(&xb[(size_t)c * HWSZ + s0 + tx]);
    }
    __syncthreads();
    float* xtb = g_xt + ((size_t)b * HWSZ + s0) * CIN;
#pragma unroll
    for (int i = 0; i < 4; i++) {
        const int srow = ty + i * 8;
        xtb[srow * CIN + tx] = tile[tx][srow];
    }
}

// ---------------------------------------------------------------------------
// Kernel 2: warp-specialized gather/HMMA pipeline, fused 3-term GEMM
//   warps 0-7: producers (quarter-warp float4 bilinear gather -> bf16 hi/lo)
//   warps 8-15: consumers (fused 3-term bf16 HMMA + direct store)
// ---------------------------------------------------------------------------
extern __shared__ char smem[];

__global__ void __launch_bounds__(THREADS, 1) mapped_conv_kernel(
    const float* __restrict__ smap,     // [OH*OW, K, 2]
    const float* __restrict__ weight,   // [COUT, CIN, K]
    const float* __restrict__ bias,     // [COUT]
    float* __restrict__ out)            // [B, COUT, OH*OW]
{
    const int tid  = threadIdx.x;
    const int warp = tid >> 5;
    const int lane = tid & 31;
    const uint32_t sbase = smem_u32(smem);

    // ---- one-time: weights -> B_HI/B_LO at [o][k*32+c] bf16
    for (int idx = tid; idx < COUT * CK; idx += THREADS) {
        const int o = idx / CK;
        const int r = idx - o * CK;      // c*KK + k
        const int c = r / KK;
        const int k = r - c * KK;
        const float w = weight[idx];
        const __nv_bfloat16 hi = __float2bfloat16(w);
        const __nv_bfloat16 lo = __float2bfloat16(w - __bfloat162float(hi));
        const int off = o * SBB + (k * CIN + c) * 2;
        *reinterpret_cast<__nv_bfloat16*>(smem + B_HI + off) = hi;
        *reinterpret_cast<__nv_bfloat16*>(smem + B_LO + off) = lo;
    }

    // ---- consumer geometry (warps 8-15): 64px x 64out, warp-tile 32x16
    const int cw = warp - 8;             // 0..7
    const int m0 = (cw >> 2) * 32;       // 0 or 32
    const int n0 = (cw & 3) * 16;        // 0,16,32,48
    const int qr = lane >> 2;
    const int qc = lane & 3;
    const uint32_t aRow = (uint32_t)((m0 + (lane & 15)) * SBB
                                     + ((lane >> 4) << 4));
    const uint32_t bRow = (uint32_t)((n0 + (lane & 7) + ((lane >> 4) << 3)) * SBB
                                     + (((lane >> 3) & 1) << 4));
    float bs[2][2];
#pragma unroll
    for (int nt = 0; nt < 2; nt++) {
        const int o0 = (n0 + nt * 8 + qc * 2) & (COUT - 1);
        bs[nt][0] = __ldg(&bias[o0]);
        bs[nt][1] = __ldg(&bias[o0 + 1]);
    }

    // ---- producer geometry (warps 0-7): quarter-warp per pixel, lane -> 4 ch
    const int hl4 = lane & 7;            // channel quad index
    const int ph4 = lane >> 3;           // pixel within quad group (0..3)

    __syncthreads();

    // ---- half-tile pipeline: produce half s, consume half s-1
    const int nt_cta   = (NT - blockIdx.x + gridDim.x - 1) / gridDim.x;
    const int nhalves  = 2 * nt_cta;

    for (int s = 0; s <= nhalves; s++) {
        // ================= producers =================
        if (warp < 8 && s < nhalves) {
            const int t   = blockIdx.x + (s >> 1) * gridDim.x;
            const int gp0 = t * TPX + (s & 1) * HPX;
            const int b   = gp0 >> 17;
            const int s0  = gp0 & (HWSZ - 1);
            const float4* __restrict__ xb4 =
                reinterpret_cast<const float4*>(g_xt + (size_t)b * HWSZ * CIN) + hl4;
            char* abuf = smem + A_BASE + (s & 1) * ABUF;

#pragma unroll 1
            for (int i = 0; i < 2; i++) {
                const int pp = warp * 8 + i * 4 + ph4;   // row in buffer [0,64)
                const float2* __restrict__ smp =
                    reinterpret_cast<const float2*>(smap) + (s0 + pp) * KK;
                char* arow_hi = abuf + pp * SBB + hl4 * 8;
                char* arow_lo = arow_hi + APLANE;

#pragma unroll
                for (int k = 0; k < KK; k++) {
                    const float2 sxy = __ldg(&smp[k]);
                    const float bx = floorf(sxy.x), by = floorf(sxy.y);
                    const float fx = sxy.x - bx,  fy = sxy.y - by;
                    const int x0 = (int)bx,  y0 = (int)by;
                    const int x1 = min(x0 + 1, WW - 1);
                    const int y1 = min(y0 + 1, HH - 1);

                    // float4 indices: (y*512+x)*8 (hl4 folded into xb4)
                    const int i00 = (y0 << 12) + (x0 << 3);
                    const int i01 = (y0 << 12) + (x1 << 3);
                    const int i10 = (y1 << 12) + (x0 << 3);
                    const int i11 = (y1 << 12) + (x1 << 3);

                    const float4 v00 = __ldg(xb4 + i00);
                    const float4 v01 = __ldg(xb4 + i01);
                    const float4 v10 = __ldg(xb4 + i10);
                    const float4 v11 = __ldg(xb4 + i11);

                    float4 v;
                    {
                        float tp, bt;
                        tp = fmaf(fx, v01.x - v00.x, v00.x);
                        bt = fmaf(fx, v11.x - v10.x, v10.x);
                        v.x = fmaf(fy, bt - tp, tp);
                        tp = fmaf(fx, v01.y - v00.y, v00.y);
                        bt = fmaf(fx, v11.y - v10.y, v10.y);
                        v.y = fmaf(fy, bt - tp, tp);
                        tp = fmaf(fx, v01.z - v00.z, v00.z);
                        bt = fmaf(fx, v11.z - v10.z, v10.z);
                        v.z = fmaf(fy, bt - tp, tp);
                        tp = fmaf(fx, v01.w - v00.w, v00.w);
                        bt = fmaf(fx, v11.w - v10.w, v10.w);
                        v.w = fmaf(fy, bt - tp, tp);
                    }

                    const __nv_bfloat162 h0 =
                        __float22bfloat162_rn(make_float2(v.x, v.y));
                    const __nv_bfloat162 h1 =
                        __float22bfloat162_rn(make_float2(v.z, v.w));
                    const float2 f0 = __bfloat1622float2(h0);
                    const float2 f1 = __bfloat1622float2(h1);
                    const __nv_bfloat162 l0 = __float22bfloat162_rn(
                        make_float2(v.x - f0.x, v.y - f0.y));
                    const __nv_bfloat162 l1 = __float22bfloat162_rn(
                        make_float2(v.z - f1.x, v.w - f1.y));

                    *reinterpret_cast<uint2*>(arow_hi + k * 64) =
                        make_uint2(bf2_u32(h0), bf2_u32(h1));
                    *reinterpret_cast<uint2*>(arow_lo + k * 64) =
                        make_uint2(bf2_u32(l0), bf2_u32(l1));
                }
            }
        }

        // ================= consumers =================
        if (warp >= 8 && s >= 1) {
            const int cs  = s - 1;
            const int t   = blockIdx.x + (cs >> 1) * gridDim.x;
            const int gp0 = t * TPX + (cs & 1) * HPX;
            const int b   = gp0 >> 17;
            const int s0  = gp0 & (HWSZ - 1);
            const uint32_t abase = sbase + A_BASE + (cs & 1) * ABUF;

            float acc[2][2][4];
#pragma unroll
            for (int a = 0; a < 2; a++)
#pragma unroll
                for (int c = 0; c < 2; c++)
#pragma unroll
                    for (int r = 0; r < 4; r++) acc[a][c][r] = 0.0f;

            const uint32_t aHi = abase + aRow;
            const uint32_t aLo = abase + APLANE + aRow;
            const uint32_t bHi = sbase + B_HI + bRow;
            const uint32_t bLo = sbase + B_LO + bRow;

            // fused 3-term loop: each fragment loaded ONCE per k-step
#pragma unroll
            for (int ks = 0; ks < 18; ks++) {
                const uint32_t kb = ks * 32;
                uint32_t ah0, ah1, ah2, ah3, ch0, ch1, ch2, ch3;
                uint32_t al0, al1, al2, al3, cl0, cl1, cl2, cl3;
                uint32_t bh0, bh1, bh2, bh3, bl0, bl1, bl2, bl3;
                ldm4(ah0, ah1, ah2, ah3, aHi + kb);
                ldm4(ch0, ch1, ch2, ch3, aHi + 16 * SBB + kb);
                ldm4(al0, al1, al2, al3, aLo + kb);
                ldm4(cl0, cl1, cl2, cl3, aLo + 16 * SBB + kb);
                ldm4(bh0, bh1, bh2, bh3, bHi + kb);
                ldm4(bl0, bl1, bl2, bl3, bLo + kb);
                // term ah*bh
                mma16816(acc[0][0], ah0, ah1, ah2, ah3, bh0, bh1);
                mma16816(acc[0][1], ah0, ah1, ah2, ah3, bh2, bh3);
                mma16816(acc[1][0], ch0, ch1, ch2, ch3, bh0, bh1);
                mma16816(acc[1][1], ch0, ch1, ch2, ch3, bh2, bh3);
                // term al*bh
                mma16816(acc[0][0], al0, al1, al2, al3, bh0, bh1);
                mma16816(acc[0][1], al0, al1, al2, al3, bh2, bh3);
                mma16816(acc[1][0], cl0, cl1, cl2, cl3, bh0, bh1);
                mma16816(acc[1][1], cl0, cl1, cl2, cl3, bh2, bh3);
                // term ah*bl
                mma16816(acc[0][0], ah0, ah1, ah2, ah3, bl0, bl1);
                mma16816(acc[0][1], ah0, ah1, ah2, ah3, bl2, bl3);
                mma16816(acc[1][0], ch0, ch1, ch2, ch3, bl0, bl1);
                mma16816(acc[1][1], ch0, ch1, ch2, ch3, bl2, bl3);
            }

            // direct stores + bias
            float* ob = out + (size_t)(b * COUT) * HWSZ + s0;
#pragma unroll
            for (int mt = 0; mt < 2; mt++) {
                const int pixA = m0 + mt * 16 + qr;
#pragma unroll
                for (int nt = 0; nt < 2; nt++) {
                    const int o0 = n0 + nt * 8 + qc * 2;
                    ob[(size_t)o0 * HWSZ + pixA]           = acc[mt][nt][0] + bs[nt][0];
                    ob[(size_t)(o0 + 1) * HWSZ + pixA]     = acc[mt][nt][1] + bs[nt][1];
                    ob[(size_t)o0 * HWSZ + pixA + 8]       = acc[mt][nt][2] + bs[nt][0];
                    ob[(size_t)(o0 + 1) * HWSZ + pixA + 8] = acc[mt][nt][3] + bs[nt][1];
                }
            }
        }

        __syncthreads();   // step boundary: buf[s&1] now full, buf[(s+1)&1] free
    }
}

// ---------------------------------------------------------------------------
// launch
// ---------------------------------------------------------------------------
extern "C" void kernel_launch(void* const* d_in, const int* in_sizes, int n_in,
                              void* d_out, int out_size) {
    const float* x = nullptr;
    const float* weight = nullptr;
    const float* bias = nullptr;
    const float* smap = nullptr;
    for (int i = 0; i < n_in; i++) {
        switch (in_sizes[i]) {
            case 8388608: x      = (const float*)d_in[i]; break;
            case 18432:   weight = (const float*)d_in[i]; break;
            case 64:      bias   = (const float*)d_in[i]; break;
            case 2359296: smap   = (const float*)d_in[i]; break;
            default: break;
        }
    }
    float* out = (float*)d_out;

    static int n_sm = 0;
    if (n_sm == 0) {
        cudaFuncSetAttribute(mapped_conv_kernel,
                             cudaFuncAttributeMaxDynamicSharedMemorySize,
                             SMEM_BYTES);
        cudaDeviceGetAttribute(&n_sm, cudaDevAttrMultiProcessorCount, 0);
        if (n_sm <= 0) n_sm = 148;
    }

    // 1) transpose x -> g_xt
    {
        dim3 grid(HWSZ / 32, BB);
        dim3 block(32, 8);
        transpose_kernel<<<grid, block>>>(x);
    }

    // 2) warp-specialized gather/GEMM pipeline: persistent, 1 CTA/SM
    mapped_conv_kernel<<<n_sm, THREADS, SMEM_BYTES>>>(smap, weight, bias, out);
}

// round 15
// speedup vs baseline: 1.6249x; 1.1112x over previous
#include <cuda_runtime.h>
#include <cuda_fp16.h>
#include <cstdint>

#define HH 256
#define WW 512
#define CIN 32
#define COUT 64
#define KK 9
#define BB 2
#define HWSZ (HH * WW)           /* 131072 */
#define NPIX (BB * HWSZ)         /* 262144 */
#define CK 288                   /* CIN*KK */
#define TPX 128                  /* pixels per tile */
#define HPX 64                   /* pixels per half (pipeline unit) */
#define NT (NPIX / TPX)          /* 2048 tiles */
#define THREADS 512

#define SB  296                  /* fp16 elements per smem row (288 + 8 pad) */
#define SBB (SB * 2)             /* 592 bytes per row; 16B-aligned, conflict-free ldmatrix */

/* ---- shared memory byte map ----
   A buffers: 2 x (hi plane + lo plane), each plane 64 rows x 592 B = 37888 B
   B: hi plane only (fp16 weights) */
#define APLANE 37888
#define ABUF   (2 * APLANE)                /* 75776 per buffer */
#define A_BASE 1024
#define B_HI   (A_BASE + 2 * ABUF)         /* 1024 + 151552 */
#define SMEM_BYTES (B_HI + COUT * SBB)     /* 190464 */

// Scratch: transposed input  xt[b][h][w][c]  (33.5 MB)
__device__ float g_xt[(size_t)NPIX * CIN];

__device__ __forceinline__ uint32_t smem_u32(const void* p) {
    uint32_t a;
    asm("{ .reg .u64 t; cvta.to.shared.u64 t, %1; cvt.u32.u64 %0, t; }"
        : "=r"(a) : "l"(p));
    return a;
}

__device__ __forceinline__ void ldm4(uint32_t& r0, uint32_t& r1,
                                     uint32_t& r2, uint32_t& r3,
                                     uint32_t addr) {
    asm volatile("ldmatrix.sync.aligned.m8n8.x4.shared.b16 {%0,%1,%2,%3}, [%4];"
                 : "=r"(r0), "=r"(r1), "=r"(r2), "=r"(r3) : "r"(addr));
}

__device__ __forceinline__ void mma16816(float* d,
                                         uint32_t a0, uint32_t a1,
                                         uint32_t a2, uint32_t a3,
                                         uint32_t b0, uint32_t b1) {
    asm volatile(
        "mma.sync.aligned.m16n8k16.row.col.f32.f16.f16.f32 "
        "{%0,%1,%2,%3}, {%4,%5,%6,%7}, {%8,%9}, {%0,%1,%2,%3};"
        : "+f"(d[0]), "+f"(d[1]), "+f"(d[2]), "+f"(d[3])
        : "r"(a0), "r"(a1), "r"(a2), "r"(a3), "r"(b0), "r"(b1));
}

__device__ __forceinline__ uint32_t h2_u32(__half2 v) {
    uint32_t u;
    __builtin_memcpy(&u, &v, 4);
    return u;
}

// ---------------------------------------------------------------------------
// Kernel 1: transpose [B, C, H, W] -> [B, H*W, C]
// ---------------------------------------------------------------------------
__global__ void transpose_kernel(const float* __restrict__ x) {
    __shared__ float tile[32][33];
    const int b  = blockIdx.y;
    const int s0 = blockIdx.x * 32;
    const int tx = threadIdx.x;
    const int ty = threadIdx.y;
    const float* xb = x + (size_t)b * CIN * HWSZ;
#pragma unroll
    for (int i = 0; i < 4; i++) {
        const int c = ty + i * 8;
        tile[c][tx] = __ldg(&xb[(size_t)c * HWSZ + s0 + tx]);
    }
    __syncthreads();
    float* xtb = g_xt + ((size_t)b * HWSZ + s0) * CIN;
#pragma unroll
    for (int i = 0; i < 4; i++) {
        const int srow = ty + i * 8;
        xtb[srow * CIN + tx] = tile[tx][srow];
    }
}

// ---------------------------------------------------------------------------
// Kernel 2: warp-specialized gather/HMMA pipeline, 2-term fp16 GEMM
//   warps 0-7: producers (quarter-warp float4 bilinear gather -> fp16 hi/lo)
//   warps 8-15: consumers (2-term fp16 HMMA, warp-tile 16px x 32out)
// ---------------------------------------------------------------------------
extern __shared__ char smem[];

__global__ void __launch_bounds__(THREADS, 1) mapped_conv_kernel(
    const float* __restrict__ smap,     // [OH*OW, K, 2]
    const float* __restrict__ weight,   // [COUT, CIN, K]
    const float* __restrict__ bias,     // [COUT]
    float* __restrict__ out)            // [B, COUT, OH*OW]
{
    const int tid  = threadIdx.x;
    const int warp = tid >> 5;
    const int lane = tid & 31;
    const uint32_t sbase = smem_u32(smem);

    // ---- one-time: weights -> B_HI (fp16) at [o][k*32+c]
    for (int idx = tid; idx < COUT * CK; idx += THREADS) {
        const int o = idx / CK;
        const int r = idx - o * CK;      // c*KK + k
        const int c = r / KK;
        const int k = r - c * KK;
        const int off = o * SBB + (k * CIN + c) * 2;
        *reinterpret_cast<__half*>(smem + B_HI + off) = __float2half(weight[idx]);
    }

    // ---- consumer geometry (warps 8-15): warp grid 4m x 2n, tile 16px x 32out
    const int cw = warp - 8;             // 0..7
    const int m0 = (cw >> 1) * 16;       // 0,16,32,48
    const int n0 = (cw & 1) * 32;        // 0 or 32
    const int qr = lane >> 2;
    const int qc = lane & 3;
    const uint32_t aRow = (uint32_t)((m0 + (lane & 15)) * SBB
                                     + ((lane >> 4) << 4));
    const uint32_t bRow = (uint32_t)((n0 + (lane & 7) + ((lane >> 4) << 3)) * SBB
                                     + (((lane >> 3) & 1) << 4));
    float bs[4][2];
#pragma unroll
    for (int j = 0; j < 4; j++) {
        const int o0 = (n0 + j * 8 + qc * 2) & (COUT - 1);
        bs[j][0] = __ldg(&bias[o0]);
        bs[j][1] = __ldg(&bias[o0 + 1]);
    }

    // ---- producer geometry (warps 0-7): quarter-warp per pixel, lane -> 4 ch
    const int hl4 = lane & 7;            // channel quad index
    const int ph4 = lane >> 3;           // pixel within quad group (0..3)

    __syncthreads();

    // ---- half-tile pipeline: produce half s, consume half s-1
    const int nt_cta   = (NT - blockIdx.x + gridDim.x - 1) / gridDim.x;
    const int nhalves  = 2 * nt_cta;

    for (int s = 0; s <= nhalves; s++) {
        // ================= producers =================
        if (warp < 8 && s < nhalves) {
            const int t   = blockIdx.x + (s >> 1) * gridDim.x;
            const int gp0 = t * TPX + (s & 1) * HPX;
            const int b   = gp0 >> 17;
            const int s0  = gp0 & (HWSZ - 1);
            const float4* __restrict__ xb4 =
                reinterpret_cast<const float4*>(g_xt + (size_t)b * HWSZ * CIN) + hl4;
            char* abuf = smem + A_BASE + (s & 1) * ABUF;

#pragma unroll 1
            for (int i = 0; i < 2; i++) {
                const int pp = warp * 8 + i * 4 + ph4;   // row in buffer [0,64)
                const float2* __restrict__ smp =
                    reinterpret_cast<const float2*>(smap) + (s0 + pp) * KK;
                char* arow_hi = abuf + pp * SBB + hl4 * 8;
                char* arow_lo = arow_hi + APLANE;

#pragma unroll
                for (int k = 0; k < KK; k++) {
                    const float2 sxy = __ldg(&smp[k]);
                    const float bx = floorf(sxy.x), by = floorf(sxy.y);
                    const float fx = sxy.x - bx,  fy = sxy.y - by;
                    const int x0 = (int)bx,  y0 = (int)by;
                    const int x1 = min(x0 + 1, WW - 1);
                    const int y1 = min(y0 + 1, HH - 1);

                    // float4 indices: (y*512+x)*8 (hl4 folded into xb4)
                    const int i00 = (y0 << 12) + (x0 << 3);
                    const int i01 = (y0 << 12) + (x1 << 3);
                    const int i10 = (y1 << 12) + (x0 << 3);
                    const int i11 = (y1 << 12) + (x1 << 3);

                    const float4 v00 = __ldg(xb4 + i00);
                    const float4 v01 = __ldg(xb4 + i01);
                    const float4 v10 = __ldg(xb4 + i10);
                    const float4 v11 = __ldg(xb4 + i11);

                    float4 v;
                    {
                        float tp, bt;
                        tp = fmaf(fx, v01.x - v00.x, v00.x);
                        bt = fmaf(fx, v11.x - v10.x, v10.x);
                        v.x = fmaf(fy, bt - tp, tp);
                        tp = fmaf(fx, v01.y - v00.y, v00.y);
                        bt = fmaf(fx, v11.y - v10.y, v10.y);
                        v.y = fmaf(fy, bt - tp, tp);
                        tp = fmaf(fx, v01.z - v00.z, v00.z);
                        bt = fmaf(fx, v11.z - v10.z, v10.z);
                        v.z = fmaf(fy, bt - tp, tp);
                        tp = fmaf(fx, v01.w - v00.w, v00.w);
                        bt = fmaf(fx, v11.w - v10.w, v10.w);
                        v.w = fmaf(fy, bt - tp, tp);
                    }

                    const __half2 h0 = __float22half2_rn(make_float2(v.x, v.y));
                    const __half2 h1 = __float22half2_rn(make_float2(v.z, v.w));
                    const float2 f0 = __half22float2(h0);
                    const float2 f1 = __half22float2(h1);
                    const __half2 l0 = __float22half2_rn(
                        make_float2(v.x - f0.x, v.y - f0.y));
                    const __half2 l1 = __float22half2_rn(
                        make_float2(v.z - f1.x, v.w - f1.y));

                    *reinterpret_cast<uint2*>(arow_hi + k * 64) =
                        make_uint2(h2_u32(h0), h2_u32(h1));
                    *reinterpret_cast<uint2*>(arow_lo + k * 64) =
                        make_uint2(h2_u32(l0), h2_u32(l1));
                }
            }
        }

        // ================= consumers =================
        if (warp >= 8 && s >= 1) {
            const int cs  = s - 1;
            const int t   = blockIdx.x + (cs >> 1) * gridDim.x;
            const int gp0 = t * TPX + (cs & 1) * HPX;
            const int b   = gp0 >> 17;
            const int s0  = gp0 & (HWSZ - 1);
            const uint32_t abase = sbase + A_BASE + (cs & 1) * ABUF;

            float acc[4][4];
#pragma unroll
            for (int j = 0; j < 4; j++)
#pragma unroll
                for (int r = 0; r < 4; r++) acc[j][r] = 0.0f;

            const uint32_t aHi = abase + aRow;
            const uint32_t aLo = abase + APLANE + aRow;
            const uint32_t bHi = sbase + B_HI + bRow;

            // fused 2-term loop: each fragment loaded ONCE per k-step
#pragma unroll
            for (int ks = 0; ks < 18; ks++) {
                const uint32_t kb = ks * 32;
                uint32_t ah0, ah1, ah2, ah3, al0, al1, al2, al3;
                uint32_t b00, b01, b02, b03, b10, b11, b12, b13;
                ldm4(ah0, ah1, ah2, ah3, aHi + kb);
                ldm4(al0, al1, al2, al3, aLo + kb);
                ldm4(b00, b01, b02, b03, bHi + kb);              // n0..n0+15
                ldm4(b10, b11, b12, b13, bHi + 16 * SBB + kb);   // n0+16..n0+31
                // term ah*b
                mma16816(acc[0], ah0, ah1, ah2, ah3, b00, b01);
                mma16816(acc[1], ah0, ah1, ah2, ah3, b02, b03);
                mma16816(acc[2], ah0, ah1, ah2, ah3, b10, b11);
                mma16816(acc[3], ah0, ah1, ah2, ah3, b12, b13);
                // term al*b
                mma16816(acc[0], al0, al1, al2, al3, b00, b01);
                mma16816(acc[1], al0, al1, al2, al3, b02, b03);
                mma16816(acc[2], al0, al1, al2, al3, b10, b11);
                mma16816(acc[3], al0, al1, al2, al3, b12, b13);
            }

            // direct stores + bias
            float* ob = out + (size_t)(b * COUT) * HWSZ + s0;
            const int pixA = m0 + qr;
#pragma unroll
            for (int j = 0; j < 4; j++) {
                const int o0 = n0 + j * 8 + qc * 2;
                ob[(size_t)o0 * HWSZ + pixA]           = acc[j][0] + bs[j][0];
                ob[(size_t)(o0 + 1) * HWSZ + pixA]     = acc[j][1] + bs[j][1];
                ob[(size_t)o0 * HWSZ + pixA + 8]       = acc[j][2] + bs[j][0];
                ob[(size_t)(o0 + 1) * HWSZ + pixA + 8] = acc[j][3] + bs[j][1];
            }
        }

        __syncthreads();   // step boundary: buf[s&1] now full, buf[(s+1)&1] free
    }
}

// ---------------------------------------------------------------------------
// launch
// ---------------------------------------------------------------------------
extern "C" void kernel_launch(void* const* d_in, const int* in_sizes, int n_in,
                              void* d_out, int out_size) {
    const float* x = nullptr;
    const float* weight = nullptr;
    const float* bias = nullptr;
    const float* smap = nullptr;
    for (int i = 0; i < n_in; i++) {
        switch (in_sizes[i]) {
            case 8388608: x      = (const float*)d_in[i]; break;
            case 18432:   weight = (const float*)d_in[i]; break;
            case 64:      bias   = (const float*)d_in[i]; break;
            case 2359296: smap   = (const float*)d_in[i]; break;
            default: break;
        }
    }
    float* out = (float*)d_out;

    static int n_sm = 0;
    if (n_sm == 0) {
        cudaFuncSetAttribute(mapped_conv_kernel,
                             cudaFuncAttributeMaxDynamicSharedMemorySize,
                             SMEM_BYTES);
        cudaDeviceGetAttribute(&n_sm, cudaDevAttrMultiProcessorCount, 0);
        if (n_sm <= 0) n_sm = 148;
    }

    // 1) transpose x -> g_xt
    {
        dim3 grid(HWSZ / 32, BB);
        dim3 block(32, 8);
        transpose_kernel<<<grid, block>>>(x);
    }

    // 2) warp-specialized gather/GEMM pipeline: persistent, 1 CTA/SM
    mapped_conv_kernel<<<n_sm, THREADS, SMEM_BYTES>>>(smap, weight, bias, out);
}

// round 16
// speedup vs baseline: 1.8968x; 1.1673x over previous
#include <cuda_runtime.h>
#include <cuda_fp16.h>
#include <cstdint>

#define HH 256
#define WW 512
#define CIN 32
#define COUT 64
#define KK 9
#define BB 2
#define HWSZ (HH * WW)           /* 131072 */
#define NPIX (BB * HWSZ)         /* 262144 */
#define CK 288                   /* CIN*KK */
#define UPX 128                  /* pixels per pipeline unit */
#define NU (NPIX / UPX)          /* 2048 units */
#define THREADS 512

#define SB  296                  /* fp16 elements per smem row (288 + 8 pad) */
#define SBB (SB * 2)             /* 592 bytes per row; 16B-aligned, conflict-free ldmatrix */

/* ---- shared memory byte map ----
   A buffers: 2 x (128 rows x 592 B) = 2 x 75776; B: fp16 weights 64 x 592 */
#define ABUF   (UPX * SBB)                 /* 75776 per buffer */
#define A_BASE 1024
#define B_HI   (A_BASE + 2 * ABUF)         /* 1024 + 151552 */
#define SMEM_BYTES (B_HI + COUT * SBB)     /* 190464 */

// Scratch: transposed input  xt[b][h][w][c]  (33.5 MB)
__device__ float g_xt[(size_t)NPIX * CIN];

__device__ __forceinline__ uint32_t smem_u32(const void* p) {
    uint32_t a;
    asm("{ .reg .u64 t; cvta.to.shared.u64 t, %1; cvt.u32.u64 %0, t; }"
        : "=r"(a) : "l"(p));
    return a;
}

__device__ __forceinline__ void ldm4(uint32_t& r0, uint32_t& r1,
                                     uint32_t& r2, uint32_t& r3,
                                     uint32_t addr) {
    asm volatile("ldmatrix.sync.aligned.m8n8.x4.shared.b16 {%0,%1,%2,%3}, [%4];"
                 : "=r"(r0), "=r"(r1), "=r"(r2), "=r"(r3) : "r"(addr));
}

__device__ __forceinline__ void mma16816(float* d,
                                         uint32_t a0, uint32_t a1,
                                         uint32_t a2, uint32_t a3,
                                         uint32_t b0, uint32_t b1) {
    asm volatile(
        "mma.sync.aligned.m16n8k16.row.col.f32.f16.f16.f32 "
        "{%0,%1,%2,%3}, {%4,%5,%6,%7}, {%8,%9}, {%0,%1,%2,%3};"
        : "+f"(d[0]), "+f"(d[1]), "+f"(d[2]), "+f"(d[3])
        : "r"(a0), "r"(a1), "r"(a2), "r"(a3), "r"(b0), "r"(b1));
}

__device__ __forceinline__ uint32_t h2_u32(__half2 v) {
    uint32_t u;
    __builtin_memcpy(&u, &v, 4);
    return u;
}

// ---------------------------------------------------------------------------
// Kernel 1: transpose [B, C, H, W] -> [B, H*W, C]
// ---------------------------------------------------------------------------
__global__ void transpose_kernel(const float* __restrict__ x) {
    __shared__ float tile[32][33];
    const int b  = blockIdx.y;
    const int s0 = blockIdx.x * 32;
    const int tx = threadIdx.x;
    const int ty = threadIdx.y;
    const float* xb = x + (size_t)b * CIN * HWSZ;
#pragma unroll
    for (int i = 0; i < 4; i++) {
        const int c = ty + i * 8;
        tile[c][tx] = __ldg(&xb[(size_t)c * HWSZ + s0 + tx]);
    }
    __syncthreads();
    float* xtb = g_xt + ((size_t)b * HWSZ + s0) * CIN;
#pragma unroll
    for (int i = 0; i < 4; i++) {
        const int srow = ty + i * 8;
        xtb[srow * CIN + tx] = tile[tx][srow];
    }
}

// ---------------------------------------------------------------------------
// Kernel 2: warp-specialized gather/HMMA pipeline, 1-term fp16 GEMM
//   warps 0-7: producers (quarter-warp float4 bilinear gather -> fp16)
//   warps 8-15: consumers (fp16 HMMA, warp-tile 32px x 32out)
// ---------------------------------------------------------------------------
extern __shared__ char smem[];

__global__ void __launch_bounds__(THREADS, 1) mapped_conv_kernel(
    const float* __restrict__ smap,     // [OH*OW, K, 2]
    const float* __restrict__ weight,   // [COUT, CIN, K]
    const float* __restrict__ bias,     // [COUT]
    float* __restrict__ out)            // [B, COUT, OH*OW]
{
    const int tid  = threadIdx.x;
    const int warp = tid >> 5;
    const int lane = tid & 31;
    const uint32_t sbase = smem_u32(smem);

    // ---- one-time: weights -> B_HI (fp16) at [o][k*32+c]
    for (int idx = tid; idx < COUT * CK; idx += THREADS) {
        const int o = idx / CK;
        const int r = idx - o * CK;      // c*KK + k
        const int c = r / KK;
        const int k = r - c * KK;
        const int off = o * SBB + (k * CIN + c) * 2;
        *reinterpret_cast<__half*>(smem + B_HI + off) = __float2half(weight[idx]);
    }

    // ---- consumer geometry (warps 8-15): warp grid 4m x 2n, tile 32px x 32out
    const int cw = warp - 8;             // 0..7
    const int m0 = (cw >> 1) * 32;       // 0,32,64,96
    const int n0 = (cw & 1) * 32;        // 0 or 32
    const int qr = lane >> 2;
    const int qc = lane & 3;
    const uint32_t aRow = (uint32_t)((m0 + (lane & 15)) * SBB
                                     + ((lane >> 4) << 4));
    const uint32_t bRow = (uint32_t)((n0 + (lane & 7) + ((lane >> 4) << 3)) * SBB
                                     + (((lane >> 3) & 1) << 4));
    float bs[4][2];
#pragma unroll
    for (int j = 0; j < 4; j++) {
        const int o0 = (n0 + j * 8 + qc * 2) & (COUT - 1);
        bs[j][0] = __ldg(&bias[o0]);
        bs[j][1] = __ldg(&bias[o0 + 1]);
    }

    // ---- producer geometry (warps 0-7): quarter-warp per pixel, lane -> 4 ch
    const int hl4 = lane & 7;            // channel quad index
    const int ph4 = lane >> 3;           // pixel within quad group (0..3)

    __syncthreads();

    // ---- unit pipeline: produce unit s, consume unit s-1 (ping-pong)
    const int nu_cta = (NU - blockIdx.x + gridDim.x - 1) / gridDim.x;

    for (int s = 0; s <= nu_cta; s++) {
        // ================= producers =================
        if (warp < 8 && s < nu_cta) {
            const int gp0 = (blockIdx.x + s * gridDim.x) * UPX;
            const int b   = gp0 >> 17;
            const int s0  = gp0 & (HWSZ - 1);
            const float4* __restrict__ xb4 =
                reinterpret_cast<const float4*>(g_xt + (size_t)b * HWSZ * CIN) + hl4;
            char* abuf = smem + A_BASE + (s & 1) * ABUF;

#pragma unroll 1
            for (int i = 0; i < 4; i++) {
                const int pp = warp * 16 + i * 4 + ph4;   // row in buffer [0,128)
                const float2* __restrict__ smp =
                    reinterpret_cast<const float2*>(smap) + (s0 + pp) * KK;
                char* arow = abuf + pp * SBB + hl4 * 8;

#pragma unroll
                for (int k = 0; k < KK; k++) {
                    const float2 sxy = __ldg(&smp[k]);
                    const float bx = floorf(sxy.x), by = floorf(sxy.y);
                    const float fx = sxy.x - bx,  fy = sxy.y - by;
                    const int x0 = (int)bx,  y0 = (int)by;
                    const int x1 = min(x0 + 1, WW - 1);
                    const int y1 = min(y0 + 1, HH - 1);

                    // float4 indices: (y*512+x)*8 (hl4 folded into xb4)
                    const int i00 = (y0 << 12) + (x0 << 3);
                    const int i01 = (y0 << 12) + (x1 << 3);
                    const int i10 = (y1 << 12) + (x0 << 3);
                    const int i11 = (y1 << 12) + (x1 << 3);

                    const float4 v00 = __ldg(xb4 + i00);
                    const float4 v01 = __ldg(xb4 + i01);
                    const float4 v10 = __ldg(xb4 + i10);
                    const float4 v11 = __ldg(xb4 + i11);

                    float4 v;
                    {
                        float tp, bt;
                        tp = fmaf(fx, v01.x - v00.x, v00.x);
                        bt = fmaf(fx, v11.x - v10.x, v10.x);
                        v.x = fmaf(fy, bt - tp, tp);
                        tp = fmaf(fx, v01.y - v00.y, v00.y);
                        bt = fmaf(fx, v11.y - v10.y, v10.y);
                        v.y = fmaf(fy, bt - tp, tp);
                        tp = fmaf(fx, v01.z - v00.z, v00.z);
                        bt = fmaf(fx, v11.z - v10.z, v10.z);
                        v.z = fmaf(fy, bt - tp, tp);
                        tp = fmaf(fx, v01.w - v00.w, v00.w);
                        bt = fmaf(fx, v11.w - v10.w, v10.w);
                        v.w = fmaf(fy, bt - tp, tp);
                    }

                    const __half2 h0 = __float22half2_rn(make_float2(v.x, v.y));
                    const __half2 h1 = __float22half2_rn(make_float2(v.z, v.w));
                    *reinterpret_cast<uint2*>(arow + k * 64) =
                        make_uint2(h2_u32(h0), h2_u32(h1));
                }
            }
        }

        // ================= consumers =================
        if (warp >= 8 && s >= 1) {
            const int gp0 = (blockIdx.x + (s - 1) * gridDim.x) * UPX;
            const int b   = gp0 >> 17;
            const int s0  = gp0 & (HWSZ - 1);
            const uint32_t abase = sbase + A_BASE + ((s - 1) & 1) * ABUF;

            float acc[2][4][4];
#pragma unroll
            for (int m = 0; m < 2; m++)
#pragma unroll
                for (int j = 0; j < 4; j++)
#pragma unroll
                    for (int r = 0; r < 4; r++) acc[m][j][r] = 0.0f;

            const uint32_t aA = abase + aRow;
            const uint32_t bB = sbase + B_HI + bRow;

#pragma unroll
            for (int ks = 0; ks < 18; ks++) {
                const uint32_t kb = ks * 32;
                uint32_t a0, a1, a2, a3, c0, c1, c2, c3;
                uint32_t b00, b01, b02, b03, b10, b11, b12, b13;
                ldm4(a0, a1, a2, a3, aA + kb);                  // px m0..m0+15
                ldm4(c0, c1, c2, c3, aA + 16 * SBB + kb);       // px m0+16..+31
                ldm4(b00, b01, b02, b03, bB + kb);              // out n0..+15
                ldm4(b10, b11, b12, b13, bB + 16 * SBB + kb);   // out n0+16..+31
                mma16816(acc[0][0], a0, a1, a2, a3, b00, b01);
                mma16816(acc[0][1], a0, a1, a2, a3, b02, b03);
                mma16816(acc[0][2], a0, a1, a2, a3, b10, b11);
                mma16816(acc[0][3], a0, a1, a2, a3, b12, b13);
                mma16816(acc[1][0], c0, c1, c2, c3, b00, b01);
                mma16816(acc[1][1], c0, c1, c2, c3, b02, b03);
                mma16816(acc[1][2], c0, c1, c2, c3, b10, b11);
                mma16816(acc[1][3], c0, c1, c2, c3, b12, b13);
            }

            // direct stores + bias
            float* ob = out + (size_t)(b * COUT) * HWSZ + s0;
#pragma unroll
            for (int m = 0; m < 2; m++) {
                const int pixA = m0 + m * 16 + qr;
#pragma unroll
                for (int j = 0; j < 4; j++) {
                    const int o0 = n0 + j * 8 + qc * 2;
                    ob[(size_t)o0 * HWSZ + pixA]           = acc[m][j][0] + bs[j][0];
                    ob[(size_t)(o0 + 1) * HWSZ + pixA]     = acc[m][j][1] + bs[j][1];
                    ob[(size_t)o0 * HWSZ + pixA + 8]       = acc[m][j][2] + bs[j][0];
                    ob[(size_t)(o0 + 1) * HWSZ + pixA + 8] = acc[m][j][3] + bs[j][1];
                }
            }
        }

        __syncthreads();   // step boundary: buf[s&1] full, buf[(s+1)&1] free
    }
}

// ---------------------------------------------------------------------------
// launch
// ---------------------------------------------------------------------------
extern "C" void kernel_launch(void* const* d_in, const int* in_sizes, int n_in,
                              void* d_out, int out_size) {
    const float* x = nullptr;
    const float* weight = nullptr;
    const float* bias = nullptr;
    const float* smap = nullptr;
    for (int i = 0; i < n_in; i++) {
        switch (in_sizes[i]) {
            case 8388608: x      = (const float*)d_in[i]; break;
            case 18432:   weight = (const float*)d_in[i]; break;
            case 64:      bias   = (const float*)d_in[i]; break;
            case 2359296: smap   = (const float*)d_in[i]; break;
            default: break;
        }
    }
    float* out = (float*)d_out;

    static int n_sm = 0;
    if (n_sm == 0) {
        cudaFuncSetAttribute(mapped_conv_kernel,
                             cudaFuncAttributeMaxDynamicSharedMemorySize,
                             SMEM_BYTES);
        cudaDeviceGetAttribute(&n_sm, cudaDevAttrMultiProcessorCount, 0);
        if (n_sm <= 0) n_sm = 148;
    }

    // 1) transpose x -> g_xt
    {
        dim3 grid(HWSZ / 32, BB);
        dim3 block(32, 8);
        transpose_kernel<<<grid, block>>>(x);
    }

    // 2) warp-specialized gather/GEMM pipeline: persistent, 1 CTA/SM
    mapped_conv_kernel<<<n_sm, THREADS, SMEM_BYTES>>>(smap, weight, bias, out);
}